// round 14
// baseline (speedup 1.0000x reference)
#include <cuda_runtime.h>
#include <cstdint>

#define THREADS 512
#define ELEMS   16384
#define CHUNK   4
#define NCHUNK  (ELEMS / 4 / THREADS / CHUNK)   // 2
#define KSEL    32
#define CAP     2048
#define THRESH  2.5f
#define KEY_MIN 0xC0200000u                     // f2key(2.5f)
#define NBINS   1024
#define EQCAP   64

// Order-preserving float -> uint32 key (ascending float <-> ascending unsigned)
__device__ __forceinline__ unsigned f2key(float f) {
    unsigned u = __float_as_uint(f);
    return (u & 0x80000000u) ? ~u : (u | 0x80000000u);
}
__device__ __forceinline__ float key2relu(unsigned k) {
    return (k & 0x80000000u) ? __uint_as_float(k ^ 0x80000000u) : 0.0f;
}
__device__ __forceinline__ int key2bin(unsigned k) {
    unsigned off = (k - KEY_MIN) >> 15;
    return off > (NBINS - 1u) ? (NBINS - 1) : (int)off;
}

// 256-bin selector (cold path): unique b with F(b) >= k > F(b+1). Warp 0.
__device__ __forceinline__ void select_bin256(const unsigned* hist,
                                              volatile unsigned* s_prefix,
                                              volatile int* s_k,
                                              unsigned pfx, int shift, int tid)
{
    if (tid < 32) {
        const int lane = tid;
        unsigned hh[8];
        int lsum = 0;
        #pragma unroll
        for (int c = 0; c < 8; ++c) { hh[c] = hist[lane * 8 + c]; lsum += (int)hh[c]; }
        int suf = lsum;
        #pragma unroll
        for (int off = 1; off < 32; off <<= 1) {
            int v = __shfl_down_sync(0xFFFFFFFFu, suf, off);
            if (lane + off < 32) suf += v;
        }
        const int above = suf - lsum;
        const int k = *s_k;
        int F = above;
        int foundb = -1, Fnext_at_found = 0;
        #pragma unroll
        for (int c = 7; c >= 0; --c) {
            int Fnext = F;
            F += (int)hh[c];
            if (F >= k && Fnext < k) { foundb = lane * 8 + c; Fnext_at_found = Fnext; }
        }
        if (foundb >= 0) {
            *s_prefix = pfx | ((unsigned)foundb << shift);
            *s_k = k - Fnext_at_found;
        }
    }
}

// 1024-bin selector (fast path): unique b with F(b) >= KSEL > F(b+1). Warp 0.
__device__ __forceinline__ void select_bin1024(const unsigned* hist,
                                               volatile int* s_bin,
                                               volatile int* s_need, int tid)
{
    if (tid < 32) {
        const int lane = tid;
        unsigned hh[32];
        int lsum = 0;
        #pragma unroll
        for (int c = 0; c < 32; c += 4) {
            uint4 q = ((const uint4*)hist)[(lane * 32 + c) / 4];
            hh[c] = q.x; hh[c+1] = q.y; hh[c+2] = q.z; hh[c+3] = q.w;
            lsum += (int)(q.x + q.y + q.z + q.w);
        }
        int suf = lsum;
        #pragma unroll
        for (int off = 1; off < 32; off <<= 1) {
            int v = __shfl_down_sync(0xFFFFFFFFu, suf, off);
            if (lane + off < 32) suf += v;
        }
        int F = suf - lsum;                // count in bins above this lane's chunk
        int foundb = -1, Fnext_at_found = 0;
        #pragma unroll
        for (int c = 31; c >= 0; --c) {
            int Fnext = F;
            F += (int)hh[c];
            if (F >= KSEL && Fnext < KSEL) { foundb = lane * 32 + c; Fnext_at_found = Fnext; }
        }
        if (foundb >= 0) {
            *s_bin  = foundb;
            *s_need = KSEL - Fnext_at_found;
        }
    }
}

__global__ __launch_bounds__(THREADS, 4)
void splittopk_kernel(const float* __restrict__ x, float* __restrict__ out)
{
    __shared__ unsigned       ckeys[CAP];    //  8 KB
    __shared__ unsigned short cidx[CAP];     //  4 KB
    __shared__ unsigned hist[NBINS];         //  4 KB
    __shared__ unsigned eq_key[EQCAP];
    __shared__ int      eq_idx[EQCAP];
    __shared__ int s_cnt;
    __shared__ int s_bin;
    __shared__ int s_need;
    __shared__ unsigned s_prefix;
    __shared__ int s_k;
    __shared__ int s_eqcnt;

    const int tid = threadIdx.x;
    const long long base = (long long)blockIdx.x * ELEMS;
    const float4* __restrict__ x4 = (const float4*)(x + base);
    float4* __restrict__ o4 = (float4*)(out + base);
    const float4 z4 = make_float4(0.f, 0.f, 0.f, 0.f);

    if (tid == 0) { s_cnt = 0; s_prefix = 0u; s_k = KSEL; s_eqcnt = 0; }
    #pragma unroll
    for (int h = tid; h < NBINS; h += THREADS) hist[h] = 0u;
    __syncthreads();                                           // B1

    // ---- stream: zero-stores first (independent, drain via store buffer),
    //      then batched loads, then compact + fused hist ----
    #pragma unroll
    for (int ch = 0; ch < NCHUNK; ++ch) {
        #pragma unroll
        for (int j = 0; j < CHUNK; ++j)
            __stcs(&o4[(ch * CHUNK + j) * THREADS + tid], z4);
        float4 r[CHUNK];
        #pragma unroll
        for (int j = 0; j < CHUNK; ++j)
            r[j] = __ldcs(&x4[(ch * CHUNK + j) * THREADS + tid]);
        #pragma unroll
        for (int j = 0; j < CHUNK; ++j) {
            const int p = (ch * CHUNK + j) * THREADS + tid;
            float vv[4] = {r[j].x, r[j].y, r[j].z, r[j].w};
            int nc = (vv[0] > THRESH) + (vv[1] > THRESH) +
                     (vv[2] > THRESH) + (vv[3] > THRESH);
            if (nc) {
                int pos = atomicAdd(&s_cnt, nc);
                #pragma unroll
                for (int c = 0; c < 4; ++c) {
                    if (vv[c] > THRESH) {
                        unsigned k = f2key(vv[c]);
                        atomicAdd(&hist[key2bin(k)], 1u);     // fused histogram
                        if (pos < CAP) {
                            ckeys[pos] = k;
                            cidx[pos]  = (unsigned short)(p * 4 + c);
                        }
                        ++pos;
                    }
                }
            }
        }
    }
    __syncthreads();                                           // B2

    const int cnt = s_cnt;

    if (cnt >= KSEL && cnt <= CAP) {
        // ======== FAST PATH: select directly from fused histogram ========
        select_bin1024(hist, &s_bin, &s_need, tid);
        __syncthreads();                                       // B3

        const int b    = s_bin;
        const int need = s_need;     // 1..32 winners inside bin b

        for (int i = tid; i < cnt; i += THREADS) {
            unsigned k = ckeys[i];
            int bi = key2bin(k);
            if (bi > b) {
                out[base + cidx[i]] = key2relu(k);   // strict winner
            } else if (bi == b) {
                int pq = atomicAdd(&s_eqcnt, 1);
                if (pq < EQCAP) { eq_key[pq] = k; eq_idx[pq] = cidx[i]; }
            }
        }
        __syncthreads();                                       // B4

        const int m = s_eqcnt;       // bin-b population (>= need)
        if (m <= EQCAP) {
            if (m == need) {
                if (tid < m) out[base + eq_idx[tid]] = key2relu(eq_key[tid]);
            } else if (tid < m) {
                // exact rank in tiny set: higher key first, ties -> smaller index
                unsigned k = eq_key[tid];
                int my = eq_idx[tid];
                int rank = 0;
                for (int j = 0; j < m; ++j) {
                    unsigned kj = eq_key[j];
                    rank += (kj > k) || (kj == k && eq_idx[j] < my);
                }
                if (rank < need) out[base + my] = key2relu(k);
            }
        } else {
            // extremely rare: bin-b overflow -> exact O(cnt) ranking fallback
            for (int i = tid; i < cnt; i += THREADS) {
                unsigned k = ckeys[i];
                if (key2bin(k) == b) {
                    int my = cidx[i];
                    int rank = 0;
                    for (int j = 0; j < cnt; ++j) {
                        unsigned kj = ckeys[j];
                        if (key2bin(kj) == b &&
                            (kj > k || (kj == k && cidx[j] < my)))
                            ++rank;
                    }
                    if (rank < need) out[base + my] = key2relu(k);
                }
            }
        }
    } else {
        // ======== COLD PATH: exact full radix-select from global (rare) ========
        #pragma unroll
        for (int pass = 0; pass < 4; ++pass) {
            const int shift = 24 - pass * 8;
            if (tid < 256) hist[tid] = 0u;
            __syncthreads();
            const unsigned pmask = (pass == 0) ? 0u : (0xFFFFFFFFu << (shift + 8));
            const unsigned pfx = s_prefix;
            for (int i = tid; i < ELEMS; i += THREADS) {
                unsigned k = f2key(x[base + i]);
                if ((k & pmask) == pfx)
                    atomicAdd(&hist[(k >> shift) & 255u], 1u);
            }
            __syncthreads();
            select_bin256(hist, &s_prefix, &s_k, pfx, shift, tid);
            __syncthreads();
        }
        const unsigned T = s_prefix;
        const int kneed  = s_k;
        const float vT   = key2relu(T);

        for (int i = tid; i < ELEMS; i += THREADS) {
            unsigned k = f2key(x[base + i]);
            if (k > T) {
                out[base + i] = key2relu(k);
            } else if (k == T) {
                int pq = atomicAdd(&s_eqcnt, 1);
                if (pq < EQCAP) eq_idx[pq] = i;
            }
        }
        __syncthreads();

        const int eqc = s_eqcnt;
        if (eqc == kneed && eqc <= EQCAP) {
            if (tid < eqc) out[base + eq_idx[tid]] = vT;
        } else {
            for (int i = tid; i < ELEMS; i += THREADS) {
                if (f2key(x[base + i]) == T) {
                    int rank = 0;
                    for (int j = 0; j < i; ++j) rank += (f2key(x[base + j]) == T);
                    if (rank < kneed) out[base + i] = vT;
                }
            }
        }
    }
}

extern "C" void kernel_launch(void* const* d_in, const int* in_sizes, int n_in,
                              void* d_out, int out_size) {
    const float* x = (const float*)d_in[0];
    float* out = (float*)d_out;
    int nblocks = out_size / ELEMS;   // 4096 rows * 2 partitions = 8192
    splittopk_kernel<<<nblocks, THREADS>>>(x, out);
}

// round 15
// speedup vs baseline: 1.0150x; 1.0150x over previous
#include <cuda_runtime.h>
#include <cstdint>

#define THREADS 512
#define ELEMS   16384
#define CHUNK   4
#define NCHUNK  (ELEMS / 4 / THREADS / CHUNK)   // 2
#define KSEL    32
#define CAP     2048
#define THRESH  2.5f
#define KEY_MIN 0xC0200000u                     // f2key(2.5f)
#define NBINS   1024
#define EQCAP   64

// Order-preserving float -> uint32 key (ascending float <-> ascending unsigned)
__device__ __forceinline__ unsigned f2key(float f) {
    unsigned u = __float_as_uint(f);
    return (u & 0x80000000u) ? ~u : (u | 0x80000000u);
}
__device__ __forceinline__ float key2relu(unsigned k) {
    return (k & 0x80000000u) ? __uint_as_float(k ^ 0x80000000u) : 0.0f;
}
__device__ __forceinline__ int key2bin(unsigned k) {
    unsigned off = (k - KEY_MIN) >> 15;
    return off > (NBINS - 1u) ? (NBINS - 1) : (int)off;
}

// 256-bin selector (cold path): unique b with F(b) >= k > F(b+1). Warp 0.
__device__ __forceinline__ void select_bin256(const unsigned* hist,
                                              volatile unsigned* s_prefix,
                                              volatile int* s_k,
                                              unsigned pfx, int shift, int tid)
{
    if (tid < 32) {
        const int lane = tid;
        unsigned hh[8];
        int lsum = 0;
        #pragma unroll
        for (int c = 0; c < 8; ++c) { hh[c] = hist[lane * 8 + c]; lsum += (int)hh[c]; }
        int suf = lsum;
        #pragma unroll
        for (int off = 1; off < 32; off <<= 1) {
            int v = __shfl_down_sync(0xFFFFFFFFu, suf, off);
            if (lane + off < 32) suf += v;
        }
        const int above = suf - lsum;
        const int k = *s_k;
        int F = above;
        int foundb = -1, Fnext_at_found = 0;
        #pragma unroll
        for (int c = 7; c >= 0; --c) {
            int Fnext = F;
            F += (int)hh[c];
            if (F >= k && Fnext < k) { foundb = lane * 8 + c; Fnext_at_found = Fnext; }
        }
        if (foundb >= 0) {
            *s_prefix = pfx | ((unsigned)foundb << shift);
            *s_k = k - Fnext_at_found;
        }
    }
}

// 1024-bin selector (fast path): unique b with F(b) >= KSEL > F(b+1). Warp 0.
__device__ __forceinline__ void select_bin1024(const unsigned* hist,
                                               volatile int* s_bin,
                                               volatile int* s_need, int tid)
{
    if (tid < 32) {
        const int lane = tid;
        unsigned hh[32];
        int lsum = 0;
        #pragma unroll
        for (int c = 0; c < 32; c += 4) {
            uint4 q = ((const uint4*)hist)[(lane * 32 + c) / 4];
            hh[c] = q.x; hh[c+1] = q.y; hh[c+2] = q.z; hh[c+3] = q.w;
            lsum += (int)(q.x + q.y + q.z + q.w);
        }
        int suf = lsum;
        #pragma unroll
        for (int off = 1; off < 32; off <<= 1) {
            int v = __shfl_down_sync(0xFFFFFFFFu, suf, off);
            if (lane + off < 32) suf += v;
        }
        int F = suf - lsum;                // count in bins above this lane's chunk
        int foundb = -1, Fnext_at_found = 0;
        #pragma unroll
        for (int c = 31; c >= 0; --c) {
            int Fnext = F;
            F += (int)hh[c];
            if (F >= KSEL && Fnext < KSEL) { foundb = lane * 32 + c; Fnext_at_found = Fnext; }
        }
        if (foundb >= 0) {
            *s_bin  = foundb;
            *s_need = KSEL - Fnext_at_found;
        }
    }
}

__global__ __launch_bounds__(THREADS, 4)
void splittopk_kernel(const float* __restrict__ x, float* __restrict__ out)
{
    __shared__ unsigned       ckeys[CAP];    //  8 KB
    __shared__ unsigned short cidx[CAP];     //  4 KB
    __shared__ unsigned hist[NBINS];         //  4 KB
    __shared__ unsigned eq_key[EQCAP];
    __shared__ int      eq_idx[EQCAP];
    __shared__ int s_cnt;
    __shared__ int s_bin;
    __shared__ int s_need;
    __shared__ unsigned s_prefix;
    __shared__ int s_k;
    __shared__ int s_eqcnt;

    const int tid = threadIdx.x;
    const long long base = (long long)blockIdx.x * ELEMS;
    const float4* __restrict__ x4 = (const float4*)(x + base);
    float4* __restrict__ o4 = (float4*)(out + base);
    const float4 z4 = make_float4(0.f, 0.f, 0.f, 0.f);

    if (tid == 0) { s_cnt = 0; s_prefix = 0u; s_k = KSEL; s_eqcnt = 0; }
    #pragma unroll
    for (int h = tid; h < NBINS; h += THREADS) hist[h] = 0u;
    __syncthreads();                                           // B1

    // ---- stream: batched loads first, streaming zero stores, compact + fused hist ----
    #pragma unroll
    for (int ch = 0; ch < NCHUNK; ++ch) {
        float4 r[CHUNK];
        #pragma unroll
        for (int j = 0; j < CHUNK; ++j)
            r[j] = __ldcs(&x4[(ch * CHUNK + j) * THREADS + tid]);
        #pragma unroll
        for (int j = 0; j < CHUNK; ++j)
            __stcs(&o4[(ch * CHUNK + j) * THREADS + tid], z4);
        #pragma unroll
        for (int j = 0; j < CHUNK; ++j) {
            const int p = (ch * CHUNK + j) * THREADS + tid;
            float vv[4] = {r[j].x, r[j].y, r[j].z, r[j].w};
            int nc = (vv[0] > THRESH) + (vv[1] > THRESH) +
                     (vv[2] > THRESH) + (vv[3] > THRESH);
            if (nc) {
                int pos = atomicAdd(&s_cnt, nc);
                #pragma unroll
                for (int c = 0; c < 4; ++c) {
                    if (vv[c] > THRESH) {
                        unsigned k = f2key(vv[c]);
                        atomicAdd(&hist[key2bin(k)], 1u);     // fused histogram
                        if (pos < CAP) {
                            ckeys[pos] = k;
                            cidx[pos]  = (unsigned short)(p * 4 + c);
                        }
                        ++pos;
                    }
                }
            }
        }
    }
    __syncthreads();                                           // B2

    const int cnt = s_cnt;

    if (cnt >= KSEL && cnt <= CAP) {
        // ======== FAST PATH: select directly from fused histogram ========
        select_bin1024(hist, &s_bin, &s_need, tid);
        __syncthreads();                                       // B3

        const int b    = s_bin;
        const int need = s_need;     // 1..32 winners inside bin b

        for (int i = tid; i < cnt; i += THREADS) {
            unsigned k = ckeys[i];
            int bi = key2bin(k);
            if (bi > b) {
                out[base + cidx[i]] = key2relu(k);   // strict winner
            } else if (bi == b) {
                int pq = atomicAdd(&s_eqcnt, 1);
                if (pq < EQCAP) { eq_key[pq] = k; eq_idx[pq] = cidx[i]; }
            }
        }
        __syncthreads();                                       // B4

        const int m = s_eqcnt;       // bin-b population (>= need)
        if (m <= EQCAP) {
            if (m == need) {
                if (tid < m) out[base + eq_idx[tid]] = key2relu(eq_key[tid]);
            } else if (tid < m) {
                // exact rank in tiny set: higher key first, ties -> smaller index
                unsigned k = eq_key[tid];
                int my = eq_idx[tid];
                int rank = 0;
                for (int j = 0; j < m; ++j) {
                    unsigned kj = eq_key[j];
                    rank += (kj > k) || (kj == k && eq_idx[j] < my);
                }
                if (rank < need) out[base + my] = key2relu(k);
            }
        } else {
            // extremely rare: bin-b overflow -> exact O(cnt) ranking fallback
            for (int i = tid; i < cnt; i += THREADS) {
                unsigned k = ckeys[i];
                if (key2bin(k) == b) {
                    int my = cidx[i];
                    int rank = 0;
                    for (int j = 0; j < cnt; ++j) {
                        unsigned kj = ckeys[j];
                        if (key2bin(kj) == b &&
                            (kj > k || (kj == k && cidx[j] < my)))
                            ++rank;
                    }
                    if (rank < need) out[base + my] = key2relu(k);
                }
            }
        }
    } else {
        // ======== COLD PATH: exact full radix-select from global (rare) ========
        #pragma unroll
        for (int pass = 0; pass < 4; ++pass) {
            const int shift = 24 - pass * 8;
            if (tid < 256) hist[tid] = 0u;
            __syncthreads();
            const unsigned pmask = (pass == 0) ? 0u : (0xFFFFFFFFu << (shift + 8));
            const unsigned pfx = s_prefix;
            for (int i = tid; i < ELEMS; i += THREADS) {
                unsigned k = f2key(x[base + i]);
                if ((k & pmask) == pfx)
                    atomicAdd(&hist[(k >> shift) & 255u], 1u);
            }
            __syncthreads();
            select_bin256(hist, &s_prefix, &s_k, pfx, shift, tid);
            __syncthreads();
        }
        const unsigned T = s_prefix;
        const int kneed  = s_k;
        const float vT   = key2relu(T);

        for (int i = tid; i < ELEMS; i += THREADS) {
            unsigned k = f2key(x[base + i]);
            if (k > T) {
                out[base + i] = key2relu(k);
            } else if (k == T) {
                int pq = atomicAdd(&s_eqcnt, 1);
                if (pq < EQCAP) eq_idx[pq] = i;
            }
        }
        __syncthreads();

        const int eqc = s_eqcnt;
        if (eqc == kneed && eqc <= EQCAP) {
            if (tid < eqc) out[base + eq_idx[tid]] = vT;
        } else {
            for (int i = tid; i < ELEMS; i += THREADS) {
                if (f2key(x[base + i]) == T) {
                    int rank = 0;
                    for (int j = 0; j < i; ++j) rank += (f2key(x[base + j]) == T);
                    if (rank < kneed) out[base + i] = vT;
                }
            }
        }
    }
}

extern "C" void kernel_launch(void* const* d_in, const int* in_sizes, int n_in,
                              void* d_out, int out_size) {
    const float* x = (const float*)d_in[0];
    float* out = (float*)d_out;
    int nblocks = out_size / ELEMS;   // 4096 rows * 2 partitions = 8192
    splittopk_kernel<<<nblocks, THREADS>>>(x, out);
}

// round 16
// speedup vs baseline: 1.0245x; 1.0094x over previous
#include <cuda_runtime.h>
#include <cstdint>

#define THREADS 512
#define ELEMS   16384
#define CHUNK   4
#define NCHUNK  (ELEMS / 4 / THREADS / CHUNK)   // 2
#define KSEL    32
#define CAP     2048
#define THRESH  1.75f
#define KEY_MIN 0xBFE00000u                     // f2key(1.75f)
#define NBINS   1024
#define EQCAP   64

// Order-preserving float -> uint32 key (ascending float <-> ascending unsigned)
__device__ __forceinline__ unsigned f2key(float f) {
    unsigned u = __float_as_uint(f);
    return (u & 0x80000000u) ? ~u : (u | 0x80000000u);
}
__device__ __forceinline__ float key2relu(unsigned k) {
    return (k & 0x80000000u) ? __uint_as_float(k ^ 0x80000000u) : 0.0f;
}
__device__ __forceinline__ int key2bin(unsigned k) {
    unsigned off = (k - KEY_MIN) >> 15;
    return off > (NBINS - 1u) ? (NBINS - 1) : (int)off;
}

// 256-bin selector (cold path): unique b with F(b) >= k > F(b+1). Warp 0.
__device__ __forceinline__ void select_bin256(const unsigned* hist,
                                              volatile unsigned* s_prefix,
                                              volatile int* s_k,
                                              unsigned pfx, int shift, int tid)
{
    if (tid < 32) {
        const int lane = tid;
        unsigned hh[8];
        int lsum = 0;
        #pragma unroll
        for (int c = 0; c < 8; ++c) { hh[c] = hist[lane * 8 + c]; lsum += (int)hh[c]; }
        int suf = lsum;
        #pragma unroll
        for (int off = 1; off < 32; off <<= 1) {
            int v = __shfl_down_sync(0xFFFFFFFFu, suf, off);
            if (lane + off < 32) suf += v;
        }
        const int above = suf - lsum;
        const int k = *s_k;
        int F = above;
        int foundb = -1, Fnext_at_found = 0;
        #pragma unroll
        for (int c = 7; c >= 0; --c) {
            int Fnext = F;
            F += (int)hh[c];
            if (F >= k && Fnext < k) { foundb = lane * 8 + c; Fnext_at_found = Fnext; }
        }
        if (foundb >= 0) {
            *s_prefix = pfx | ((unsigned)foundb << shift);
            *s_k = k - Fnext_at_found;
        }
    }
}

// 1024-bin selector (fast path): unique b with F(b) >= KSEL > F(b+1). Warp 0.
__device__ __forceinline__ void select_bin1024(const unsigned* hist,
                                               volatile int* s_bin,
                                               volatile int* s_need, int tid)
{
    if (tid < 32) {
        const int lane = tid;
        unsigned hh[32];
        int lsum = 0;
        #pragma unroll
        for (int c = 0; c < 32; c += 4) {
            uint4 q = ((const uint4*)hist)[(lane * 32 + c) / 4];
            hh[c] = q.x; hh[c+1] = q.y; hh[c+2] = q.z; hh[c+3] = q.w;
            lsum += (int)(q.x + q.y + q.z + q.w);
        }
        int suf = lsum;
        #pragma unroll
        for (int off = 1; off < 32; off <<= 1) {
            int v = __shfl_down_sync(0xFFFFFFFFu, suf, off);
            if (lane + off < 32) suf += v;
        }
        int F = suf - lsum;                // count in bins above this lane's chunk
        int foundb = -1, Fnext_at_found = 0;
        #pragma unroll
        for (int c = 31; c >= 0; --c) {
            int Fnext = F;
            F += (int)hh[c];
            if (F >= KSEL && Fnext < KSEL) { foundb = lane * 32 + c; Fnext_at_found = Fnext; }
        }
        if (foundb >= 0) {
            *s_bin  = foundb;
            *s_need = KSEL - Fnext_at_found;
        }
    }
}

__global__ __launch_bounds__(THREADS, 4)
void splittopk_kernel(const float* __restrict__ x, float* __restrict__ out)
{
    __shared__ unsigned       ckeys[CAP];    //  8 KB
    __shared__ unsigned short cidx[CAP];     //  4 KB
    __shared__ unsigned hist[NBINS];         //  4 KB
    __shared__ unsigned eq_key[EQCAP];
    __shared__ int      eq_idx[EQCAP];
    __shared__ int s_cnt;
    __shared__ int s_bin;
    __shared__ int s_need;
    __shared__ unsigned s_prefix;
    __shared__ int s_k;
    __shared__ int s_eqcnt;

    const int tid = threadIdx.x;
    const long long base = (long long)blockIdx.x * ELEMS;
    const float4* __restrict__ x4 = (const float4*)(x + base);
    float4* __restrict__ o4 = (float4*)(out + base);

    if (tid == 0) { s_cnt = 0; s_prefix = 0u; s_k = KSEL; s_eqcnt = 0; }
    #pragma unroll
    for (int h = tid; h < NBINS; h += THREADS) hist[h] = 0u;
    __syncthreads();                                           // B1

    // ---- stream: batched loads, zero stores, ballot-free compaction ----
    #pragma unroll
    for (int ch = 0; ch < NCHUNK; ++ch) {
        float4 r[CHUNK];
        #pragma unroll
        for (int j = 0; j < CHUNK; ++j)
            r[j] = __ldcs(&x4[(ch * CHUNK + j) * THREADS + tid]);
        #pragma unroll
        for (int j = 0; j < CHUNK; ++j)
            o4[(ch * CHUNK + j) * THREADS + tid] = make_float4(0.f, 0.f, 0.f, 0.f);
        #pragma unroll
        for (int j = 0; j < CHUNK; ++j) {
            const int p = (ch * CHUNK + j) * THREADS + tid;
            float vv[4] = {r[j].x, r[j].y, r[j].z, r[j].w};
            int nc = (vv[0] > THRESH) + (vv[1] > THRESH) +
                     (vv[2] > THRESH) + (vv[3] > THRESH);
            if (nc) {
                int pos = atomicAdd(&s_cnt, nc);
                #pragma unroll
                for (int c = 0; c < 4; ++c) {
                    if (vv[c] > THRESH) {
                        if (pos < CAP) {
                            ckeys[pos] = f2key(vv[c]);
                            cidx[pos]  = (unsigned short)(p * 4 + c);
                        }
                        ++pos;
                    }
                }
            }
        }
    }
    __syncthreads();                                           // B2

    const int cnt = s_cnt;

    if (cnt >= KSEL && cnt <= CAP) {
        // ======== FAST PATH: one histogram pass, tiny exact in-bin rank ========
        for (int i = tid; i < cnt; i += THREADS)
            atomicAdd(&hist[key2bin(ckeys[i])], 1u);
        __syncthreads();                                       // B3
        select_bin1024(hist, &s_bin, &s_need, tid);
        __syncthreads();                                       // B4

        const int b    = s_bin;
        const int need = s_need;     // 1..32 winners inside bin b

        for (int i = tid; i < cnt; i += THREADS) {
            unsigned k = ckeys[i];
            int bi = key2bin(k);
            if (bi > b) {
                out[base + cidx[i]] = key2relu(k);   // strict winner
            } else if (bi == b) {
                int pq = atomicAdd(&s_eqcnt, 1);
                if (pq < EQCAP) { eq_key[pq] = k; eq_idx[pq] = cidx[i]; }
            }
        }
        __syncthreads();                                       // B5

        const int m = s_eqcnt;       // bin-b population (>= need)
        if (m <= EQCAP) {
            if (m == need) {
                if (tid < m) out[base + eq_idx[tid]] = key2relu(eq_key[tid]);
            } else if (tid < m) {
                // exact rank in tiny set: higher key first, ties -> smaller index
                unsigned k = eq_key[tid];
                int my = eq_idx[tid];
                int rank = 0;
                for (int j = 0; j < m; ++j) {
                    unsigned kj = eq_key[j];
                    rank += (kj > k) || (kj == k && eq_idx[j] < my);
                }
                if (rank < need) out[base + my] = key2relu(k);
            }
        } else {
            // extremely rare: bin-b overflow -> exact O(cnt) ranking fallback
            for (int i = tid; i < cnt; i += THREADS) {
                unsigned k = ckeys[i];
                if (key2bin(k) == b) {
                    int my = cidx[i];
                    int rank = 0;
                    for (int j = 0; j < cnt; ++j) {
                        unsigned kj = ckeys[j];
                        if (key2bin(kj) == b &&
                            (kj > k || (kj == k && cidx[j] < my)))
                            ++rank;
                    }
                    if (rank < need) out[base + my] = key2relu(k);
                }
            }
        }
    } else {
        // ======== COLD PATH: exact full radix-select from global (rare) ========
        #pragma unroll
        for (int pass = 0; pass < 4; ++pass) {
            const int shift = 24 - pass * 8;
            if (tid < 256) hist[tid] = 0u;
            __syncthreads();
            const unsigned pmask = (pass == 0) ? 0u : (0xFFFFFFFFu << (shift + 8));
            const unsigned pfx = s_prefix;
            for (int i = tid; i < ELEMS; i += THREADS) {
                unsigned k = f2key(x[base + i]);
                if ((k & pmask) == pfx)
                    atomicAdd(&hist[(k >> shift) & 255u], 1u);
            }
            __syncthreads();
            select_bin256(hist, &s_prefix, &s_k, pfx, shift, tid);
            __syncthreads();
        }
        const unsigned T = s_prefix;
        const int kneed  = s_k;
        const float vT   = key2relu(T);

        for (int i = tid; i < ELEMS; i += THREADS) {
            unsigned k = f2key(x[base + i]);
            if (k > T) {
                out[base + i] = key2relu(k);
            } else if (k == T) {
                int pq = atomicAdd(&s_eqcnt, 1);
                if (pq < EQCAP) eq_idx[pq] = i;
            }
        }
        __syncthreads();

        const int eqc = s_eqcnt;
        if (eqc == kneed && eqc <= EQCAP) {
            if (tid < eqc) out[base + eq_idx[tid]] = vT;
        } else {
            for (int i = tid; i < ELEMS; i += THREADS) {
                if (f2key(x[base + i]) == T) {
                    int rank = 0;
                    for (int j = 0; j < i; ++j) rank += (f2key(x[base + j]) == T);
                    if (rank < kneed) out[base + i] = vT;
                }
            }
        }
    }
}

extern "C" void kernel_launch(void* const* d_in, const int* in_sizes, int n_in,
                              void* d_out, int out_size) {
    const float* x = (const float*)d_in[0];
    float* out = (float*)d_out;
    int nblocks = out_size / ELEMS;   // 4096 rows * 2 partitions = 8192
    splittopk_kernel<<<nblocks, THREADS>>>(x, out);
}

// round 17
// speedup vs baseline: 1.0314x; 1.0067x over previous
#include <cuda_runtime.h>
#include <cstdint>

#define THREADS 512
#define ELEMS   16384
#define CHUNK   4
#define NCHUNK  (ELEMS / 4 / THREADS / CHUNK)   // 2
#define KSEL    32
#define CAP     2048
#define THRESH  2.5f
#define KEY_MIN 0xC0200000u                     // f2key(2.5f)
#define NBINS   1024
#define EQCAP   64

// Order-preserving float -> uint32 key (ascending float <-> ascending unsigned)
__device__ __forceinline__ unsigned f2key(float f) {
    unsigned u = __float_as_uint(f);
    return (u & 0x80000000u) ? ~u : (u | 0x80000000u);
}
__device__ __forceinline__ float key2relu(unsigned k) {
    return (k & 0x80000000u) ? __uint_as_float(k ^ 0x80000000u) : 0.0f;
}
__device__ __forceinline__ int key2bin(unsigned k) {
    unsigned off = (k - KEY_MIN) >> 15;
    return off > (NBINS - 1u) ? (NBINS - 1) : (int)off;
}

// 256-bin selector (cold path): unique b with F(b) >= k > F(b+1). Warp 0.
__device__ __forceinline__ void select_bin256(const unsigned* hist,
                                              volatile unsigned* s_prefix,
                                              volatile int* s_k,
                                              unsigned pfx, int shift, int tid)
{
    if (tid < 32) {
        const int lane = tid;
        unsigned hh[8];
        int lsum = 0;
        #pragma unroll
        for (int c = 0; c < 8; ++c) { hh[c] = hist[lane * 8 + c]; lsum += (int)hh[c]; }
        int suf = lsum;
        #pragma unroll
        for (int off = 1; off < 32; off <<= 1) {
            int v = __shfl_down_sync(0xFFFFFFFFu, suf, off);
            if (lane + off < 32) suf += v;
        }
        const int above = suf - lsum;
        const int k = *s_k;
        int F = above;
        int foundb = -1, Fnext_at_found = 0;
        #pragma unroll
        for (int c = 7; c >= 0; --c) {
            int Fnext = F;
            F += (int)hh[c];
            if (F >= k && Fnext < k) { foundb = lane * 8 + c; Fnext_at_found = Fnext; }
        }
        if (foundb >= 0) {
            *s_prefix = pfx | ((unsigned)foundb << shift);
            *s_k = k - Fnext_at_found;
        }
    }
}

// 1024-bin selector (fast path): unique b with F(b) >= KSEL > F(b+1). Warp 0.
__device__ __forceinline__ void select_bin1024(const unsigned* hist,
                                               volatile int* s_bin,
                                               volatile int* s_need, int tid)
{
    if (tid < 32) {
        const int lane = tid;
        unsigned hh[32];
        int lsum = 0;
        #pragma unroll
        for (int c = 0; c < 32; c += 4) {
            uint4 q = ((const uint4*)hist)[(lane * 32 + c) / 4];
            hh[c] = q.x; hh[c+1] = q.y; hh[c+2] = q.z; hh[c+3] = q.w;
            lsum += (int)(q.x + q.y + q.z + q.w);
        }
        int suf = lsum;
        #pragma unroll
        for (int off = 1; off < 32; off <<= 1) {
            int v = __shfl_down_sync(0xFFFFFFFFu, suf, off);
            if (lane + off < 32) suf += v;
        }
        int F = suf - lsum;                // count in bins above this lane's chunk
        int foundb = -1, Fnext_at_found = 0;
        #pragma unroll
        for (int c = 31; c >= 0; --c) {
            int Fnext = F;
            F += (int)hh[c];
            if (F >= KSEL && Fnext < KSEL) { foundb = lane * 32 + c; Fnext_at_found = Fnext; }
        }
        if (foundb >= 0) {
            *s_bin  = foundb;
            *s_need = KSEL - Fnext_at_found;
        }
    }
}

__global__ __launch_bounds__(THREADS, 4)
void splittopk_kernel(const float* __restrict__ x, float* __restrict__ out)
{
    __shared__ unsigned       ckeys[CAP];    //  8 KB
    __shared__ unsigned short cidx[CAP];     //  4 KB
    __shared__ unsigned hist[NBINS];         //  4 KB
    __shared__ unsigned eq_key[EQCAP];
    __shared__ int      eq_idx[EQCAP];
    __shared__ int s_cnt;
    __shared__ int s_bin;
    __shared__ int s_need;
    __shared__ unsigned s_prefix;
    __shared__ int s_k;
    __shared__ int s_eqcnt;

    const int tid = threadIdx.x;
    const long long base = (long long)blockIdx.x * ELEMS;
    const float4* __restrict__ x4 = (const float4*)(x + base);
    float4* __restrict__ o4 = (float4*)(out + base);

    if (tid == 0) { s_cnt = 0; s_prefix = 0u; s_k = KSEL; s_eqcnt = 0; }
    #pragma unroll
    for (int h = tid; h < NBINS; h += THREADS) hist[h] = 0u;
    __syncthreads();                                           // B1

    // ---- stream: batched loads, zero stores, ballot-free compaction ----
    #pragma unroll
    for (int ch = 0; ch < NCHUNK; ++ch) {
        float4 r[CHUNK];
        #pragma unroll
        for (int j = 0; j < CHUNK; ++j)
            r[j] = __ldcs(&x4[(ch * CHUNK + j) * THREADS + tid]);
        #pragma unroll
        for (int j = 0; j < CHUNK; ++j)
            o4[(ch * CHUNK + j) * THREADS + tid] = make_float4(0.f, 0.f, 0.f, 0.f);
        #pragma unroll
        for (int j = 0; j < CHUNK; ++j) {
            const int p = (ch * CHUNK + j) * THREADS + tid;
            float vv[4] = {r[j].x, r[j].y, r[j].z, r[j].w};
            int nc = (vv[0] > THRESH) + (vv[1] > THRESH) +
                     (vv[2] > THRESH) + (vv[3] > THRESH);
            if (nc) {
                int pos = atomicAdd(&s_cnt, nc);
                #pragma unroll
                for (int c = 0; c < 4; ++c) {
                    if (vv[c] > THRESH) {
                        if (pos < CAP) {
                            ckeys[pos] = f2key(vv[c]);
                            cidx[pos]  = (unsigned short)(p * 4 + c);
                        }
                        ++pos;
                    }
                }
            }
        }
    }
    __syncthreads();                                           // B2

    const int cnt = s_cnt;

    if (cnt >= KSEL && cnt <= CAP) {
        // ======== FAST PATH: one histogram pass, tiny exact in-bin rank ========
        for (int i = tid; i < cnt; i += THREADS)
            atomicAdd(&hist[key2bin(ckeys[i])], 1u);
        __syncthreads();                                       // B3
        select_bin1024(hist, &s_bin, &s_need, tid);
        __syncthreads();                                       // B4

        const int b    = s_bin;
        const int need = s_need;     // 1..32 winners inside bin b

        for (int i = tid; i < cnt; i += THREADS) {
            unsigned k = ckeys[i];
            int bi = key2bin(k);
            if (bi > b) {
                out[base + cidx[i]] = key2relu(k);   // strict winner
            } else if (bi == b) {
                int pq = atomicAdd(&s_eqcnt, 1);
                if (pq < EQCAP) { eq_key[pq] = k; eq_idx[pq] = cidx[i]; }
            }
        }
        __syncthreads();                                       // B5

        const int m = s_eqcnt;       // bin-b population (>= need)
        if (m <= EQCAP) {
            if (m == need) {
                if (tid < m) out[base + eq_idx[tid]] = key2relu(eq_key[tid]);
            } else if (tid < m) {
                // exact rank in tiny set: higher key first, ties -> smaller index
                unsigned k = eq_key[tid];
                int my = eq_idx[tid];
                int rank = 0;
                for (int j = 0; j < m; ++j) {
                    unsigned kj = eq_key[j];
                    rank += (kj > k) || (kj == k && eq_idx[j] < my);
                }
                if (rank < need) out[base + my] = key2relu(k);
            }
        } else {
            // extremely rare: bin-b overflow -> exact O(cnt) ranking fallback
            for (int i = tid; i < cnt; i += THREADS) {
                unsigned k = ckeys[i];
                if (key2bin(k) == b) {
                    int my = cidx[i];
                    int rank = 0;
                    for (int j = 0; j < cnt; ++j) {
                        unsigned kj = ckeys[j];
                        if (key2bin(kj) == b &&
                            (kj > k || (kj == k && cidx[j] < my)))
                            ++rank;
                    }
                    if (rank < need) out[base + my] = key2relu(k);
                }
            }
        }
    } else {
        // ======== COLD PATH: exact full radix-select from global (rare) ========
        #pragma unroll
        for (int pass = 0; pass < 4; ++pass) {
            const int shift = 24 - pass * 8;
            if (tid < 256) hist[tid] = 0u;
            __syncthreads();
            const unsigned pmask = (pass == 0) ? 0u : (0xFFFFFFFFu << (shift + 8));
            const unsigned pfx = s_prefix;
            for (int i = tid; i < ELEMS; i += THREADS) {
                unsigned k = f2key(x[base + i]);
                if ((k & pmask) == pfx)
                    atomicAdd(&hist[(k >> shift) & 255u], 1u);
            }
            __syncthreads();
            select_bin256(hist, &s_prefix, &s_k, pfx, shift, tid);
            __syncthreads();
        }
        const unsigned T = s_prefix;
        const int kneed  = s_k;
        const float vT   = key2relu(T);

        for (int i = tid; i < ELEMS; i += THREADS) {
            unsigned k = f2key(x[base + i]);
            if (k > T) {
                out[base + i] = key2relu(k);
            } else if (k == T) {
                int pq = atomicAdd(&s_eqcnt, 1);
                if (pq < EQCAP) eq_idx[pq] = i;
            }
        }
        __syncthreads();

        const int eqc = s_eqcnt;
        if (eqc == kneed && eqc <= EQCAP) {
            if (tid < eqc) out[base + eq_idx[tid]] = vT;
        } else {
            for (int i = tid; i < ELEMS; i += THREADS) {
                if (f2key(x[base + i]) == T) {
                    int rank = 0;
                    for (int j = 0; j < i; ++j) rank += (f2key(x[base + j]) == T);
                    if (rank < kneed) out[base + i] = vT;
                }
            }
        }
    }
}

extern "C" void kernel_launch(void* const* d_in, const int* in_sizes, int n_in,
                              void* d_out, int out_size) {
    const float* x = (const float*)d_in[0];
    float* out = (float*)d_out;
    int nblocks = out_size / ELEMS;   // 4096 rows * 2 partitions = 8192
    splittopk_kernel<<<nblocks, THREADS>>>(x, out);
}